// round 6
// baseline (speedup 1.0000x reference)
#include <cuda_runtime.h>
#include <cuda_bf16.h>
#include <cstdint>

// ---------------- problem constants ----------------
#define BB 4
#define HH 128
#define HID 7168
#define QL 1536
#define KVL 512
#define DN 128
#define DR 64
#define DV 128
#define DQK 192
#define TT 1025          // PAST + 1
#define QROWS (HH*DQK)   // 24576
#define CTXD (HH*DV)     // 16384
#define QFD 576          // KVL + DR
#define NSPLIT 4
#define SCP2 260
// 1/sqrt(192)
#define SCALE_QK 0.07216878364870323f

// ---------------- device scratch ----------------
__device__ float g_qa[BB*QL];
__device__ float g_qan[BB*QL];
__device__ float g_q[BB*QROWS];
__device__ float g_ckv[BB*QFD];
__device__ float g_qfull[BB*HH*QFD];
__device__ float g_ctx[BB*CTXD];
__device__ float g_ct[BB*QFD*TT];             // transposed cache [b][k][t]
__device__ float g_pm[BB*HH*NSPLIT];          // per-split running max
__device__ float g_ps[BB*HH*NSPLIT];          // per-split exp-sum
__device__ float g_pctx[(size_t)BB*HH*NSPLIT*KVL]; // per-split unnormalized ctx

// position_ids may be int32 or int64
__device__ __forceinline__ int get_pos(const int* __restrict__ p, int b)
{
    bool is64 = (p[1] == 0) && (p[3] == 0) && (p[0] != 0);
    return is64 ? p[2*b] : p[b];
}

// ---------------- GEMV v2: smem-staged X, 2 rows per warp ----------------
// out[b][row] = A[row,:] . X[b,:]   for b in 0..3
template<int NW>
__global__ void gemv2_kernel(const float4* __restrict__ A, const float4* __restrict__ X,
                             float* __restrict__ out, int K4, int outStride)
{
    __shared__ float4 sx[4][512];   // 32 KB tile of X
    int tid = threadIdx.x, w = tid >> 5, lane = tid & 31;
    int row0 = (blockIdx.x * NW + w) * 2;
    const float4* a0 = A + (size_t)row0 * K4;
    const float4* a1 = a0 + K4;
    float p00=0.f,p01=0.f,p02=0.f,p03=0.f;
    float p10=0.f,p11=0.f,p12=0.f,p13=0.f;
    for (int kt = 0; kt < K4; kt += 512) {
        int cur = min(512, K4 - kt);
        __syncthreads();
        #pragma unroll
        for (int b = 0; b < 4; b++)
            for (int i = tid; i < cur; i += NW*32)
                sx[b][i] = X[(size_t)b*K4 + kt + i];
        __syncthreads();
        #pragma unroll 4
        for (int i = lane; i < cur; i += 32) {
            float4 av0 = a0[kt + i];
            float4 av1 = a1[kt + i];
            float4 x0 = sx[0][i];
            float4 x1 = sx[1][i];
            float4 x2 = sx[2][i];
            float4 x3 = sx[3][i];
            p00 += av0.x*x0.x + av0.y*x0.y + av0.z*x0.z + av0.w*x0.w;
            p10 += av1.x*x0.x + av1.y*x0.y + av1.z*x0.z + av1.w*x0.w;
            p01 += av0.x*x1.x + av0.y*x1.y + av0.z*x1.z + av0.w*x1.w;
            p11 += av1.x*x1.x + av1.y*x1.y + av1.z*x1.z + av1.w*x1.w;
            p02 += av0.x*x2.x + av0.y*x2.y + av0.z*x2.z + av0.w*x2.w;
            p12 += av1.x*x2.x + av1.y*x2.y + av1.z*x2.z + av1.w*x2.w;
            p03 += av0.x*x3.x + av0.y*x3.y + av0.z*x3.z + av0.w*x3.w;
            p13 += av1.x*x3.x + av1.y*x3.y + av1.z*x3.z + av1.w*x3.w;
        }
    }
    #pragma unroll
    for (int off = 16; off; off >>= 1) {
        p00 += __shfl_xor_sync(0xffffffffu, p00, off);
        p01 += __shfl_xor_sync(0xffffffffu, p01, off);
        p02 += __shfl_xor_sync(0xffffffffu, p02, off);
        p03 += __shfl_xor_sync(0xffffffffu, p03, off);
        p10 += __shfl_xor_sync(0xffffffffu, p10, off);
        p11 += __shfl_xor_sync(0xffffffffu, p11, off);
        p12 += __shfl_xor_sync(0xffffffffu, p12, off);
        p13 += __shfl_xor_sync(0xffffffffu, p13, off);
    }
    if (lane == 0) {
        out[(size_t)0*outStride + row0] = p00;
        out[(size_t)1*outStride + row0] = p01;
        out[(size_t)2*outStride + row0] = p02;
        out[(size_t)3*outStride + row0] = p03;
        out[(size_t)0*outStride + row0+1] = p10;
        out[(size_t)1*outStride + row0+1] = p11;
        out[(size_t)2*outStride + row0+1] = p12;
        out[(size_t)3*outStride + row0+1] = p13;
    }
}

// ---------------- rmsnorm of q_a ----------------
__global__ void rmsnorm_q_kernel(const float* __restrict__ gamma)
{
    int b = blockIdx.x, tid = threadIdx.x;
    float ss = 0.f;
    for (int i = tid; i < QL; i += 256) { float v = g_qa[b*QL+i]; ss += v*v; }
    #pragma unroll
    for (int off = 16; off; off >>= 1) ss += __shfl_xor_sync(0xffffffffu, ss, off);
    __shared__ float r[8];
    __shared__ float s_rs;
    if ((tid & 31) == 0) r[tid >> 5] = ss;
    __syncthreads();
    if (tid == 0) {
        float t = 0.f;
        #pragma unroll
        for (int i = 0; i < 8; i++) t += r[i];
        s_rs = rsqrtf(t / (float)QL + 1e-6f);
    }
    __syncthreads();
    for (int i = tid; i < QL; i += 256) g_qan[b*QL+i] = g_qa[b*QL+i] * s_rs * gamma[i];
}

// ---------------- ckv postprocess: rmsnorm + k_pe RoPE -> new cache row ----------------
// Writes the row into out_cache AND into the t=1024 column of g_ct.
__global__ void ckv_post_kernel(const float* __restrict__ gkv, const float* __restrict__ cosT,
                                const float* __restrict__ sinT, const int* __restrict__ posw,
                                float* __restrict__ out_cache)
{
    int b = blockIdx.x, tid = threadIdx.x;
    const float* cv = g_ckv + b*QFD;
    float ss = 0.f;
    for (int i = tid; i < KVL; i += 256) { float v = cv[i]; ss += v*v; }
    #pragma unroll
    for (int off = 16; off; off >>= 1) ss += __shfl_xor_sync(0xffffffffu, ss, off);
    __shared__ float r[8];
    __shared__ float s_rs;
    if ((tid & 31) == 0) r[tid >> 5] = ss;
    __syncthreads();
    if (tid == 0) {
        float t = 0.f;
        #pragma unroll
        for (int i = 0; i < 8; i++) t += r[i];
        s_rs = rsqrtf(t / (float)KVL + 1e-6f);
    }
    __syncthreads();
    float* dst = out_cache + ((size_t)b*TT + (TT-1)) * QFD;
    float* ctb = g_ct + (size_t)b*QFD*TT + (TT-1);
    for (int i = tid; i < KVL; i += 256) {
        float v = cv[i] * s_rs * gkv[i];
        dst[i] = v;
        ctb[(size_t)i*TT] = v;
    }
    if (tid < DR) {
        int d = tid;
        int p = get_pos(posw, b);
        float v  = cv[KVL + d];
        float pr = (d < 32) ? -cv[KVL + d + 32] : cv[KVL + d - 32];
        float res = v * cosT[(size_t)p*DR + d] + pr * sinT[(size_t)p*DR + d];
        dst[KVL + d] = res;
        ctb[(size_t)(KVL + d)*TT] = res;
    }
}

// ---------------- copy past cache rows into output cache ----------------
__global__ void copy_cache_kernel(const float4* __restrict__ past, float* __restrict__ out_cache)
{
    int t = blockIdx.x, b = blockIdx.y, i = threadIdx.x;   // 144 threads
    float4* dst = (float4*)(out_cache + ((size_t)b*TT + t) * QFD);
    dst[i] = past[((size_t)b*(TT-1) + t) * (QFD/4) + i];
}

// ---------------- absorption + fused q_pe RoPE -> g_qfull (pre-scaled) ----------------
__global__ void absorb_rope_kernel(const float* __restrict__ w_kvb,
                                   const float* __restrict__ cosT, const float* __restrict__ sinT,
                                   const int* __restrict__ posw)
{
    int h = blockIdx.x, c = threadIdx.x;   // 512 threads
    __shared__ float qs[4][DN];
    int b0 = c >> 7, d0 = c & 127;
    qs[b0][d0] = g_q[(size_t)b0*QROWS + h*DQK + d0];
    __syncthreads();
    float acc[4] = {0.f, 0.f, 0.f, 0.f};
    const float* wk = w_kvb + (size_t)h*256*KVL + c;
    #pragma unroll 4
    for (int d = 0; d < DN; d++) {
        float wv = wk[(size_t)d*KVL];
        acc[0] += qs[0][d]*wv; acc[1] += qs[1][d]*wv;
        acc[2] += qs[2][d]*wv; acc[3] += qs[3][d]*wv;
    }
    #pragma unroll
    for (int b = 0; b < 4; b++)
        g_qfull[((size_t)(b*HH + h))*QFD + c] = acc[b] * SCALE_QK;
    if (c < 256) {   // fused RoPE: (b, d) = (c>>6, c&63)
        int b = c >> 6, d = c & 63;
        int p = get_pos(posw, b);
        const float* qp = g_q + (size_t)b*QROWS + h*DQK + DN;
        float v  = qp[d];
        float pr = (d < 32) ? -qp[d+32] : qp[d-32];
        g_qfull[((size_t)(b*HH + h))*QFD + KVL + d] =
            (v * cosT[(size_t)p*DR + d] + pr * sinT[(size_t)p*DR + d]) * SCALE_QK;
    }
}

// ---------------- transpose past -> ct[b][k][t] for t < 1024 ----------------
__global__ void transpose_cache_kernel(const float* __restrict__ past)
{
    __shared__ float tile[32][33];
    int tb = blockIdx.x * 32, kb = blockIdx.y * 32, b = blockIdx.z;
    int tx = threadIdx.x, ty = threadIdx.y;     // (32, 8)
    for (int i = ty; i < 32; i += 8) {
        int t = tb + i, k = kb + tx;
        if (k < QFD) tile[i][tx] = past[((size_t)b*(TT-1) + t)*QFD + k];
    }
    __syncthreads();
    for (int i = ty; i < 32; i += 8) {
        int k = kb + i, t = tb + tx;
        if (k < QFD) g_ct[((size_t)b*QFD + k)*TT + t] = tile[tx][i];
    }
}

// ---------------- attention split: scores + partial softmax + partial ctx ----------------
// Reads k-major scores from g_ct; reads V-rows from past (t<1024) / out_cache (t=1024).
__global__ void attn_split_kernel(const float* __restrict__ past,
                                  const float* __restrict__ out_cache,
                                  const float* __restrict__ mask)
{
    __shared__ float qsm[8*QFD];
    __shared__ float sc[8*SCP2];
    int b = blockIdx.z, split = blockIdx.y, h0 = blockIdx.x * 8, tid = threadIdx.x;
    int T0 = split * 256;
    int TE = (split == NSPLIT-1) ? TT : T0 + 256;
    int cnt = TE - T0;

    for (int i = tid; i < 8*QFD; i += 256) {
        int h = i / QFD, k = i % QFD;
        qsm[i] = g_qfull[((size_t)(b*HH + h0 + h))*QFD + k];
    }
    __syncthreads();

    // ---- phase 1: scores for t = T0 + tid ----
    {
        float acc[8];
        #pragma unroll
        for (int h = 0; h < 8; h++) acc[h] = 0.f;
        const float* ctb = g_ct + (size_t)b*QFD*TT + T0 + tid;
        for (int k = 0; k < QFD; k += 4) {
            float c0 = ctb[(size_t)k*TT];
            float c1 = ctb[(size_t)(k+1)*TT];
            float c2 = ctb[(size_t)(k+2)*TT];
            float c3 = ctb[(size_t)(k+3)*TT];
            #pragma unroll
            for (int h = 0; h < 8; h++) {
                acc[h] += qsm[h*QFD+k]*c0 + qsm[h*QFD+k+1]*c1
                        + qsm[h*QFD+k+2]*c2 + qsm[h*QFD+k+3]*c3;
            }
        }
        float mk = mask[(size_t)b*TT + T0 + tid];
        #pragma unroll
        for (int h = 0; h < 8; h++) sc[h*SCP2 + tid] = acc[h] + mk;

        if (split == NSPLIT-1 && tid < 32) {   // t = 1024 by warp 0
            const float* crow = out_cache + ((size_t)b*TT + (TT-1))*QFD;
            float mk2 = mask[(size_t)b*TT + (TT-1)];
            for (int h = 0; h < 8; h++) {
                float p = 0.f;
                for (int i = tid; i < QFD; i += 32) p += qsm[h*QFD + i]*crow[i];
                #pragma unroll
                for (int off = 16; off; off >>= 1) p += __shfl_xor_sync(0xffffffffu, p, off);
                if (tid == 0) sc[h*SCP2 + 256] = p + mk2;
            }
        }
    }
    __syncthreads();

    // ---- phase 2: local softmax (warp per head) ----
    {
        int w = tid >> 5, lane = tid & 31, h = w;
        float m = -1e30f;
        for (int t = lane; t < cnt; t += 32) m = fmaxf(m, sc[h*SCP2 + t]);
        #pragma unroll
        for (int off = 16; off; off >>= 1) m = fmaxf(m, __shfl_xor_sync(0xffffffffu, m, off));
        float s = 0.f;
        for (int t = lane; t < cnt; t += 32) {
            float e = __expf(sc[h*SCP2 + t] - m);
            sc[h*SCP2 + t] = e;
            s += e;
        }
        #pragma unroll
        for (int off = 16; off; off >>= 1) s += __shfl_xor_sync(0xffffffffu, s, off);
        if (lane == 0) {
            int idx = (b*HH + h0 + h)*NSPLIT + split;
            g_pm[idx] = m;
            g_ps[idx] = s;
        }
    }
    __syncthreads();

    // ---- phase 3: partial ctx (unnormalized), latent rows from past ----
    {
        float acc[8][2];
        #pragma unroll
        for (int h = 0; h < 8; h++) { acc[h][0] = 0.f; acc[h][1] = 0.f; }
        const float* pb = past + (size_t)b*(TT-1)*QFD;
        int c0 = tid, c1 = tid + 256;
        int tEndPast = (TE < TT) ? TE : (TT-1);
        for (int t = T0; t < tEndPast; t++) {
            const float* crow = pb + (size_t)t*QFD;
            float v0 = crow[c0], v1 = crow[c1];
            int tl = t - T0;
            #pragma unroll
            for (int h = 0; h < 8; h++) {
                float a = sc[h*SCP2 + tl];
                acc[h][0] += a*v0; acc[h][1] += a*v1;
            }
        }
        if (TE == TT) {   // t = 1024 row from out_cache
            const float* crow = out_cache + ((size_t)b*TT + (TT-1))*QFD;
            float v0 = crow[c0], v1 = crow[c1];
            #pragma unroll
            for (int h = 0; h < 8; h++) {
                float a = sc[h*SCP2 + 256];
                acc[h][0] += a*v0; acc[h][1] += a*v1;
            }
        }
        #pragma unroll
        for (int h = 0; h < 8; h++) {
            size_t base = ((size_t)(b*HH + h0 + h)*NSPLIT + split)*KVL;
            g_pctx[base + c0] = acc[h][0];
            g_pctx[base + c1] = acc[h][1];
        }
    }
}

// ---------------- fused combine + V projection (block per head) ----------------
__global__ void vproj_combine_kernel(const float* __restrict__ w_kvb)
{
    __shared__ float cl[4][KVL];   // combined normalized latent ctx, 8 KB
    int h = blockIdx.x, tid = threadIdx.x;
    {
        int bq = tid >> 6, lq = tid & 63;
        int idx = bq*HH + h;
        float m = -1e30f;
        #pragma unroll
        for (int s = 0; s < NSPLIT; s++) m = fmaxf(m, g_pm[idx*NSPLIT + s]);
        float e[NSPLIT]; float ssum = 0.f;
        #pragma unroll
        for (int s = 0; s < NSPLIT; s++) {
            e[s] = __expf(g_pm[idx*NSPLIT + s] - m);
            ssum += g_ps[idx*NSPLIT + s] * e[s];
        }
        float inv = 1.0f / ssum;
        for (int c = lq; c < KVL; c += 64) {
            float acc = 0.f;
            #pragma unroll
            for (int s = 0; s < NSPLIT; s++)
                acc += g_pctx[((size_t)idx*NSPLIT + s)*KVL + c] * e[s];
            cl[bq][c] = acc * inv;
        }
    }
    __syncthreads();
    int w = tid >> 5, lane = tid & 31;
    for (int dv = w; dv < DV; dv += 8) {
        const float* wr = w_kvb + ((size_t)(h*256 + DN + dv))*KVL;
        float p0 = 0.f, p1 = 0.f, p2 = 0.f, p3 = 0.f;
        #pragma unroll 4
        for (int i = lane; i < KVL; i += 32) {
            float wv = wr[i];
            p0 += wv * cl[0][i];
            p1 += wv * cl[1][i];
            p2 += wv * cl[2][i];
            p3 += wv * cl[3][i];
        }
        #pragma unroll
        for (int off = 16; off; off >>= 1) {
            p0 += __shfl_xor_sync(0xffffffffu, p0, off);
            p1 += __shfl_xor_sync(0xffffffffu, p1, off);
            p2 += __shfl_xor_sync(0xffffffffu, p2, off);
            p3 += __shfl_xor_sync(0xffffffffu, p3, off);
        }
        if (lane == 0) {
            g_ctx[(size_t)0*CTXD + h*DV + dv] = p0;
            g_ctx[(size_t)1*CTXD + h*DV + dv] = p1;
            g_ctx[(size_t)2*CTXD + h*DV + dv] = p2;
            g_ctx[(size_t)3*CTXD + h*DV + dv] = p3;
        }
    }
}

// ---------------- host launch (single stream, zero allocations) ----------------
extern "C" void kernel_launch(void* const* d_in, const int* in_sizes, int n_in,
                              void* d_out, int out_size)
{
    const float* x      = (const float*)d_in[0];
    const float* mask   = (const float*)d_in[1];
    const int*   posw   = (const int*)  d_in[2];
    const float* past   = (const float*)d_in[3];
    const float* cosT   = (const float*)d_in[4];
    const float* sinT   = (const float*)d_in[5];
    const float* w_qa   = (const float*)d_in[6];
    const float* gq     = (const float*)d_in[7];
    const float* w_qb   = (const float*)d_in[8];
    const float* w_kva  = (const float*)d_in[9];
    const float* gkv    = (const float*)d_in[10];
    const float* w_kvb  = (const float*)d_in[11];
    const float* w_o    = (const float*)d_in[12];

    float* out_attn  = (float*)d_out;                  // [4,1,7168]
    float* out_cache = out_attn + (size_t)BB*HID;      // [4,1025,576]

    float *p_qa, *p_qan, *p_q, *p_ckv, *p_ctx;
    cudaGetSymbolAddress((void**)&p_qa,  g_qa);
    cudaGetSymbolAddress((void**)&p_qan, g_qan);
    cudaGetSymbolAddress((void**)&p_q,   g_q);
    cudaGetSymbolAddress((void**)&p_ckv, g_ckv);
    cudaGetSymbolAddress((void**)&p_ctx, g_ctx);

    // q_a = x @ w_qa.T         (44 MB)
    gemv2_kernel<8><<<QL/16, 256>>>((const float4*)w_qa, (const float4*)x, p_qa, HID/4, QL);
    // ckv = x @ w_kva.T        (16.5 MB)
    gemv2_kernel<8><<<QFD/16, 256>>>((const float4*)w_kva, (const float4*)x, p_ckv, HID/4, QFD);
    // rmsnorm(q_a)
    rmsnorm_q_kernel<<<BB, 256>>>(gq);
    // q = q_an @ w_qb.T        (151 MB)
    gemv2_kernel<8><<<QROWS/16, 256>>>((const float4*)w_qb, (const float4*)p_qan, p_q, QL/4, QROWS);
    // new latent row -> out_cache + g_ct column
    ckv_post_kernel<<<BB, 256>>>(gkv, cosT, sinT, posw, out_cache);
    // transpose past -> g_ct (t < 1024)
    transpose_cache_kernel<<<dim3(32, (QFD+31)/32, BB), dim3(32, 8)>>>(past);
    // absorption + fused q_pe RoPE
    absorb_rope_kernel<<<HH, 512>>>(w_kvb, cosT, sinT, posw);
    // output-cache copy obligation
    copy_cache_kernel<<<dim3(TT-1, BB), QFD/4>>>((const float4*)past, out_cache);
    // attention: split-KV + fused combine/vproj
    attn_split_kernel<<<dim3(HH/8, NSPLIT, BB), 256>>>(past, out_cache, mask);
    vproj_combine_kernel<<<HH, 256>>>(w_kvb);
    // attn_out = ctx @ w_o.T   (470 MB)
    gemv2_kernel<8><<<HID/16, 256>>>((const float4*)w_o, (const float4*)p_ctx, out_attn, CTXD/4, HID);
}

// round 7
// speedup vs baseline: 1.3885x; 1.3885x over previous
#include <cuda_runtime.h>
#include <cuda_bf16.h>
#include <cstdint>

// ---------------- problem constants ----------------
#define BB 4
#define HH 128
#define HID 7168
#define QL 1536
#define KVL 512
#define DN 128
#define DR 64
#define DV 128
#define DQK 192
#define TT 1025          // PAST + 1
#define QROWS (HH*DQK)   // 24576
#define CTXD (HH*DV)     // 16384
#define QFD 576          // KVL + DR
#define NSPLIT 4
#define SCP2 260
// 1/sqrt(192)
#define SCALE_QK 0.07216878364870323f

// ---------------- device scratch ----------------
__device__ float g_qa[BB*QL];
__device__ float g_qan[BB*QL];
__device__ float g_q[BB*QROWS];
__device__ float g_ckv[BB*QFD];
__device__ float g_qfull[BB*HH*QFD];
__device__ float g_ctx[BB*CTXD];
__device__ float g_ct[BB*QFD*TT];             // transposed cache [b][k][t]
__device__ float g_pm[BB*HH*NSPLIT];
__device__ float g_ps[BB*HH*NSPLIT];
__device__ float g_pctx[(size_t)BB*HH*NSPLIT*KVL];

__device__ __forceinline__ int get_pos(const int* __restrict__ p, int b)
{
    bool is64 = (p[1] == 0) && (p[3] == 0) && (p[0] != 0);
    return is64 ? p[2*b] : p[b];
}

// ---------------- GEMV v3: smem-staged X, RW rows/warp, explicit 8-deep LDG batching ----
// requires: every smem tile size (and K4 tail) divisible by 32*U
template<int RW, int U>
__global__ void gemv3_kernel(const float4* __restrict__ A, const float4* __restrict__ X,
                             float* __restrict__ out, int K4, int outStride)
{
    static_assert(RW*U == 8, "");
    __shared__ float4 sx[4][512];   // 32 KB
    int tid = threadIdx.x, w = tid >> 5, lane = tid & 31;
    int row0 = (blockIdx.x * 8 + w) * RW;
    const float4* arow[RW];
    #pragma unroll
    for (int r = 0; r < RW; r++) arow[r] = A + (size_t)(row0 + r) * K4;
    float acc[RW][4];
    #pragma unroll
    for (int r = 0; r < RW; r++)
        #pragma unroll
        for (int b = 0; b < 4; b++) acc[r][b] = 0.f;

    for (int kt = 0; kt < K4; kt += 512) {
        int cur = min(512, K4 - kt);
        __syncthreads();
        for (int i = tid; i < cur; i += 256) {
            sx[0][i] = X[(size_t)0*K4 + kt + i];
            sx[1][i] = X[(size_t)1*K4 + kt + i];
            sx[2][i] = X[(size_t)2*K4 + kt + i];
            sx[3][i] = X[(size_t)3*K4 + kt + i];
        }
        __syncthreads();
        for (int ib = 0; ib < cur; ib += 32*U) {
            // front-batch 8 independent global loads
            float4 av[U][RW];
            #pragma unroll
            for (int u = 0; u < U; u++)
                #pragma unroll
                for (int r = 0; r < RW; r++)
                    av[u][r] = arow[r][kt + ib + u*32 + lane];
            #pragma unroll
            for (int u = 0; u < U; u++) {
                #pragma unroll
                for (int b = 0; b < 4; b++) {
                    float4 xv = sx[b][ib + u*32 + lane];
                    #pragma unroll
                    for (int r = 0; r < RW; r++)
                        acc[r][b] += av[u][r].x*xv.x + av[u][r].y*xv.y
                                   + av[u][r].z*xv.z + av[u][r].w*xv.w;
                }
            }
        }
    }
    #pragma unroll
    for (int r = 0; r < RW; r++)
        #pragma unroll
        for (int b = 0; b < 4; b++)
            #pragma unroll
            for (int off = 16; off; off >>= 1)
                acc[r][b] += __shfl_xor_sync(0xffffffffu, acc[r][b], off);
    if (lane == 0) {
        #pragma unroll
        for (int r = 0; r < RW; r++)
            #pragma unroll
            for (int b = 0; b < 4; b++)
                out[(size_t)b*outStride + row0 + r] = acc[r][b];
    }
}

// ---------------- rmsnorm of q_a ----------------
__global__ void rmsnorm_q_kernel(const float* __restrict__ gamma)
{
    int b = blockIdx.x, tid = threadIdx.x;
    float ss = 0.f;
    for (int i = tid; i < QL; i += 256) { float v = g_qa[b*QL+i]; ss += v*v; }
    #pragma unroll
    for (int off = 16; off; off >>= 1) ss += __shfl_xor_sync(0xffffffffu, ss, off);
    __shared__ float r[8];
    __shared__ float s_rs;
    if ((tid & 31) == 0) r[tid >> 5] = ss;
    __syncthreads();
    if (tid == 0) {
        float t = 0.f;
        #pragma unroll
        for (int i = 0; i < 8; i++) t += r[i];
        s_rs = rsqrtf(t / (float)QL + 1e-6f);
    }
    __syncthreads();
    for (int i = tid; i < QL; i += 256) g_qan[b*QL+i] = g_qa[b*QL+i] * s_rs * gamma[i];
}

// ---------------- fused prep: transpose(past) | copy(past->out_cache) | ckv_post ----------------
// grid = 2304 (transpose) + 2304 (copy) + 4 (ckv), 256 threads each
#define PREP_TRANS 2304
#define PREP_COPY  2304
__global__ void prep_kernel(const float* __restrict__ past,
                            float* __restrict__ out_cache,
                            const float* __restrict__ gkv, const float* __restrict__ cosT,
                            const float* __restrict__ sinT, const int* __restrict__ posw)
{
    __shared__ float tile[32][33];
    __shared__ float red[8];
    __shared__ float s_rs;
    int blk = blockIdx.x, tid = threadIdx.x;

    if (blk < PREP_TRANS) {
        // transpose past[b][t][k] -> g_ct[b][k][t], t<1024, full 32x32 tiles (576 = 18*32)
        int b = blk / 576, rem = blk % 576;
        int kb = (rem / 32) * 32, tb = (rem % 32) * 32;
        int tx = tid & 31, ty = tid >> 5;
        #pragma unroll
        for (int i = ty; i < 32; i += 8)
            tile[i][tx] = past[((size_t)b*(TT-1) + tb + i)*QFD + kb + tx];
        __syncthreads();
        #pragma unroll
        for (int i = ty; i < 32; i += 8)
            g_ct[((size_t)b*QFD + kb + i)*TT + tb + tx] = tile[tx][i];
        return;
    }
    if (blk < PREP_TRANS + PREP_COPY) {
        // copy past -> out_cache rows t<1024 as float4; 589824 f4 = 2304*256
        size_t g = (size_t)(blk - PREP_TRANS) * 256 + tid;
        int b = (int)(g / 147456);
        size_t rr = g % 147456;
        int t = (int)(rr / 144), i = (int)(rr % 144);
        ((float4*)(out_cache + ((size_t)b*TT + t)*QFD))[i] =
            ((const float4*)(past + ((size_t)b*(TT-1) + t)*QFD))[i];
        return;
    }
    // ckv_post for b = blk - 4608
    {
        int b = blk - (PREP_TRANS + PREP_COPY);
        const float* cv = g_ckv + b*QFD;
        float ss = 0.f;
        for (int i = tid; i < KVL; i += 256) { float v = cv[i]; ss += v*v; }
        #pragma unroll
        for (int off = 16; off; off >>= 1) ss += __shfl_xor_sync(0xffffffffu, ss, off);
        if ((tid & 31) == 0) red[tid >> 5] = ss;
        __syncthreads();
        if (tid == 0) {
            float t = 0.f;
            #pragma unroll
            for (int i = 0; i < 8; i++) t += red[i];
            s_rs = rsqrtf(t / (float)KVL + 1e-6f);
        }
        __syncthreads();
        float* dst = out_cache + ((size_t)b*TT + (TT-1)) * QFD;
        float* ctb = g_ct + (size_t)b*QFD*TT + (TT-1);
        for (int i = tid; i < KVL; i += 256) {
            float v = cv[i] * s_rs * gkv[i];
            dst[i] = v;
            ctb[(size_t)i*TT] = v;
        }
        if (tid < DR) {
            int d = tid;
            int p = get_pos(posw, b);
            float v  = cv[KVL + d];
            float pr = (d < 32) ? -cv[KVL + d + 32] : cv[KVL + d - 32];
            float res = v * cosT[(size_t)p*DR + d] + pr * sinT[(size_t)p*DR + d];
            dst[KVL + d] = res;
            ctb[(size_t)(KVL + d)*TT] = res;
        }
    }
}

// ---------------- absorption + fused q_pe RoPE -> g_qfull (pre-scaled) ----------------
__global__ void absorb_rope_kernel(const float* __restrict__ w_kvb,
                                   const float* __restrict__ cosT, const float* __restrict__ sinT,
                                   const int* __restrict__ posw)
{
    int h = blockIdx.x, c = threadIdx.x;   // 512 threads
    __shared__ float qs[4][DN];
    int b0 = c >> 7, d0 = c & 127;
    qs[b0][d0] = g_q[(size_t)b0*QROWS + h*DQK + d0];
    __syncthreads();
    float acc[4] = {0.f, 0.f, 0.f, 0.f};
    const float* wk = w_kvb + (size_t)h*256*KVL + c;
    #pragma unroll 4
    for (int d = 0; d < DN; d++) {
        float wv = wk[(size_t)d*KVL];
        acc[0] += qs[0][d]*wv; acc[1] += qs[1][d]*wv;
        acc[2] += qs[2][d]*wv; acc[3] += qs[3][d]*wv;
    }
    #pragma unroll
    for (int b = 0; b < 4; b++)
        g_qfull[((size_t)(b*HH + h))*QFD + c] = acc[b] * SCALE_QK;
    if (c < 256) {
        int b = c >> 6, d = c & 63;
        int p = get_pos(posw, b);
        const float* qp = g_q + (size_t)b*QROWS + h*DQK + DN;
        float v  = qp[d];
        float pr = (d < 32) ? -qp[d+32] : qp[d-32];
        g_qfull[((size_t)(b*HH + h))*QFD + KVL + d] =
            (v * cosT[(size_t)p*DR + d] + pr * sinT[(size_t)p*DR + d]) * SCALE_QK;
    }
}

// ---------------- attention split: high-ILP scores + softmax + partial ctx ----------------
__global__ void attn_split_kernel(const float* __restrict__ past,
                                  const float* __restrict__ out_cache,
                                  const float* __restrict__ mask)
{
    __shared__ __align__(16) float qsm[8*QFD];
    __shared__ __align__(16) float sc[8*SCP2];
    int b = blockIdx.z, split = blockIdx.y, h0 = blockIdx.x * 8, tid = threadIdx.x;
    int T0 = split * 256;
    int TE = (split == NSPLIT-1) ? TT : T0 + 256;
    int cnt = TE - T0;

    for (int i = tid; i < 8*QFD; i += 256) {
        int h = i / QFD, k = i % QFD;
        qsm[i] = g_qfull[((size_t)(b*HH + h0 + h))*QFD + k];
    }
    __syncthreads();

    // ---- phase 1: scores for t = T0 + tid; 8 LDG batched + float4 LDS ----
    {
        float acc[8];
        #pragma unroll
        for (int h = 0; h < 8; h++) acc[h] = 0.f;
        const float* ctb = g_ct + (size_t)b*QFD*TT + T0 + tid;
        for (int k = 0; k < QFD; k += 8) {
            float c[8];
            #pragma unroll
            for (int j = 0; j < 8; j++) c[j] = ctb[(size_t)(k+j)*TT];
            #pragma unroll
            for (int h = 0; h < 8; h++) {
                const float4* qv = reinterpret_cast<const float4*>(&qsm[h*QFD + k]);
                float4 q0 = qv[0], q1 = qv[1];
                acc[h] += q0.x*c[0] + q0.y*c[1] + q0.z*c[2] + q0.w*c[3]
                        + q1.x*c[4] + q1.y*c[5] + q1.z*c[6] + q1.w*c[7];
            }
        }
        float mk = mask[(size_t)b*TT + T0 + tid];
        #pragma unroll
        for (int h = 0; h < 8; h++) sc[h*SCP2 + tid] = acc[h] + mk;

        if (split == NSPLIT-1 && tid < 32) {   // t = 1024 by warp 0
            const float* crow = out_cache + ((size_t)b*TT + (TT-1))*QFD;
            float mk2 = mask[(size_t)b*TT + (TT-1)];
            for (int h = 0; h < 8; h++) {
                float p = 0.f;
                for (int i = tid; i < QFD; i += 32) p += qsm[h*QFD + i]*crow[i];
                #pragma unroll
                for (int off = 16; off; off >>= 1) p += __shfl_xor_sync(0xffffffffu, p, off);
                if (tid == 0) sc[h*SCP2 + 256] = p + mk2;
            }
        }
    }
    __syncthreads();

    // ---- phase 2: local softmax (warp per head) ----
    {
        int w = tid >> 5, lane = tid & 31, h = w;
        float m = -1e30f;
        for (int t = lane; t < cnt; t += 32) m = fmaxf(m, sc[h*SCP2 + t]);
        #pragma unroll
        for (int off = 16; off; off >>= 1) m = fmaxf(m, __shfl_xor_sync(0xffffffffu, m, off));
        float s = 0.f;
        for (int t = lane; t < cnt; t += 32) {
            float e = __expf(sc[h*SCP2 + t] - m);
            sc[h*SCP2 + t] = e;
            s += e;
        }
        #pragma unroll
        for (int off = 16; off; off >>= 1) s += __shfl_xor_sync(0xffffffffu, s, off);
        if (lane == 0) {
            int idx = (b*HH + h0 + h)*NSPLIT + split;
            g_pm[idx] = m;
            g_ps[idx] = s;
        }
    }
    __syncthreads();

    // ---- phase 3: partial ctx; t-unroll 4 (8 LDG batched) + float4 LDS ----
    {
        float acc[8][2];
        #pragma unroll
        for (int h = 0; h < 8; h++) { acc[h][0] = 0.f; acc[h][1] = 0.f; }
        const float* pb = past + (size_t)b*(TT-1)*QFD;
        int c0 = tid, c1 = tid + 256;
        // every split covers exactly 256 past rows
        for (int t0 = T0; t0 < T0 + 256; t0 += 4) {
            float v0[4], v1[4];
            #pragma unroll
            for (int j = 0; j < 4; j++) {
                const float* crow = pb + (size_t)(t0+j)*QFD;
                v0[j] = crow[c0];
                v1[j] = crow[c1];
            }
            int tl = t0 - T0;
            #pragma unroll
            for (int h = 0; h < 8; h++) {
                float4 a4 = *reinterpret_cast<const float4*>(&sc[h*SCP2 + tl]);
                acc[h][0] += a4.x*v0[0] + a4.y*v0[1] + a4.z*v0[2] + a4.w*v0[3];
                acc[h][1] += a4.x*v1[0] + a4.y*v1[1] + a4.z*v1[2] + a4.w*v1[3];
            }
        }
        if (TE == TT) {   // t = 1024 row from out_cache
            const float* crow = out_cache + ((size_t)b*TT + (TT-1))*QFD;
            float v0 = crow[c0], v1 = crow[c1];
            #pragma unroll
            for (int h = 0; h < 8; h++) {
                float a = sc[h*SCP2 + 256];
                acc[h][0] += a*v0; acc[h][1] += a*v1;
            }
        }
        #pragma unroll
        for (int h = 0; h < 8; h++) {
            size_t base = ((size_t)(b*HH + h0 + h)*NSPLIT + split)*KVL;
            g_pctx[base + c0] = acc[h][0];
            g_pctx[base + c1] = acc[h][1];
        }
    }
}

// ---------------- fused combine + V projection; grid (HH, 2): dv halves ----------------
__global__ void vproj_combine_kernel(const float* __restrict__ w_kvb)
{
    __shared__ float cl[4][KVL];
    int h = blockIdx.x, half = blockIdx.y, tid = threadIdx.x;
    {
        int bq = tid >> 6, lq = tid & 63;
        int idx = bq*HH + h;
        float m = -1e30f;
        #pragma unroll
        for (int s = 0; s < NSPLIT; s++) m = fmaxf(m, g_pm[idx*NSPLIT + s]);
        float e[NSPLIT]; float ssum = 0.f;
        #pragma unroll
        for (int s = 0; s < NSPLIT; s++) {
            e[s] = __expf(g_pm[idx*NSPLIT + s] - m);
            ssum += g_ps[idx*NSPLIT + s] * e[s];
        }
        float inv = 1.0f / ssum;
        for (int c = lq; c < KVL; c += 64) {
            float acc = 0.f;
            #pragma unroll
            for (int s = 0; s < NSPLIT; s++)
                acc += g_pctx[((size_t)idx*NSPLIT + s)*KVL + c] * e[s];
            cl[bq][c] = acc * inv;
        }
    }
    __syncthreads();
    int w = tid >> 5, lane = tid & 31;
    int dv = half*64 + w*8;   // each warp does 8 consecutive dv, 8 warps cover 64
    for (int d = dv; d < dv + 8; d++) {
        const float* wr = w_kvb + ((size_t)(h*256 + DN + d))*KVL;
        float p0 = 0.f, p1 = 0.f, p2 = 0.f, p3 = 0.f;
        #pragma unroll 4
        for (int i = lane; i < KVL; i += 32) {
            float wv = wr[i];
            p0 += wv * cl[0][i];
            p1 += wv * cl[1][i];
            p2 += wv * cl[2][i];
            p3 += wv * cl[3][i];
        }
        #pragma unroll
        for (int off = 16; off; off >>= 1) {
            p0 += __shfl_xor_sync(0xffffffffu, p0, off);
            p1 += __shfl_xor_sync(0xffffffffu, p1, off);
            p2 += __shfl_xor_sync(0xffffffffu, p2, off);
            p3 += __shfl_xor_sync(0xffffffffu, p3, off);
        }
        if (lane == 0) {
            g_ctx[(size_t)0*CTXD + h*DV + d] = p0;
            g_ctx[(size_t)1*CTXD + h*DV + d] = p1;
            g_ctx[(size_t)2*CTXD + h*DV + d] = p2;
            g_ctx[(size_t)3*CTXD + h*DV + d] = p3;
        }
    }
}

// ---------------- host launch (single stream, zero allocations) ----------------
extern "C" void kernel_launch(void* const* d_in, const int* in_sizes, int n_in,
                              void* d_out, int out_size)
{
    const float* x      = (const float*)d_in[0];
    const float* mask   = (const float*)d_in[1];
    const int*   posw   = (const int*)  d_in[2];
    const float* past   = (const float*)d_in[3];
    const float* cosT   = (const float*)d_in[4];
    const float* sinT   = (const float*)d_in[5];
    const float* w_qa   = (const float*)d_in[6];
    const float* gq     = (const float*)d_in[7];
    const float* w_qb   = (const float*)d_in[8];
    const float* w_kva  = (const float*)d_in[9];
    const float* gkv    = (const float*)d_in[10];
    const float* w_kvb  = (const float*)d_in[11];
    const float* w_o    = (const float*)d_in[12];

    float* out_attn  = (float*)d_out;                  // [4,1,7168]
    float* out_cache = out_attn + (size_t)BB*HID;      // [4,1025,576]

    float *p_qa, *p_qan, *p_q, *p_ckv, *p_ctx;
    cudaGetSymbolAddress((void**)&p_qa,  g_qa);
    cudaGetSymbolAddress((void**)&p_qan, g_qan);
    cudaGetSymbolAddress((void**)&p_q,   g_q);
    cudaGetSymbolAddress((void**)&p_ckv, g_ckv);
    cudaGetSymbolAddress((void**)&p_ctx, g_ctx);

    // ckv = x @ w_kva.T        (16.5 MB)  RW=2,U=4 -> 36 blocks
    gemv3_kernel<2,4><<<QFD/16, 256>>>((const float4*)w_kva, (const float4*)x, p_ckv, HID/4, QFD);
    // q_a = x @ w_qa.T         (44 MB)    96 blocks
    gemv3_kernel<2,4><<<QL/16, 256>>>((const float4*)w_qa, (const float4*)x, p_qa, HID/4, QL);
    // rmsnorm(q_a)
    rmsnorm_q_kernel<<<BB, 256>>>(gq);
    // q = q_an @ w_qb.T        (151 MB)   RW=4,U=2 -> 768 blocks
    gemv3_kernel<4,2><<<QROWS/32, 256>>>((const float4*)w_qb, (const float4*)p_qan, p_q, QL/4, QROWS);
    // fused: transpose past -> g_ct | copy past -> out_cache | ckv_post
    prep_kernel<<<PREP_TRANS + PREP_COPY + BB, 256>>>(past, out_cache, gkv, cosT, sinT, posw);
    // absorption + fused q_pe RoPE
    absorb_rope_kernel<<<HH, 512>>>(w_kvb, cosT, sinT, posw);
    // attention: split-KV
    attn_split_kernel<<<dim3(HH/8, NSPLIT, BB), 256>>>(past, out_cache, mask);
    // combine + V projection (256 blocks)
    vproj_combine_kernel<<<dim3(HH, 2), 256>>>(w_kvb);
    // attn_out = ctx @ w_o.T   (470 MB)   448 blocks
    gemv3_kernel<2,4><<<HID/16, 256>>>((const float4*)w_o, (const float4*)p_ctx, out_attn, CTXD/4, HID);
}

// round 8
// speedup vs baseline: 1.6357x; 1.1780x over previous
#include <cuda_runtime.h>
#include <cuda_bf16.h>
#include <cstdint>

// ---------------- problem constants ----------------
#define BB 4
#define HH 128
#define HID 7168
#define QL 1536
#define KVL 512
#define DN 128
#define DR 64
#define DV 128
#define DQK 192
#define TT 1025          // PAST + 1
#define QROWS (HH*DQK)   // 24576
#define CTXD (HH*DV)     // 16384
#define QFD 576          // KVL + DR
#define NSPLIT 4
#define SCP2 260
// 1/sqrt(192)
#define SCALE_QK 0.07216878364870323f

// ---------------- device scratch ----------------
__device__ float g_qa[BB*QL];
__device__ float g_qan[BB*QL];
__device__ float g_q[BB*QROWS];
__device__ float g_ckv[BB*QFD];
__device__ float g_qfull[BB*HH*QFD];
__device__ float g_ctx[BB*CTXD];
__device__ float g_ct[BB*QFD*TT];             // transposed cache [b][k][t]
__device__ float g_pm[BB*HH*NSPLIT];
__device__ float g_ps[BB*HH*NSPLIT];
__device__ float g_pctx[(size_t)BB*HH*NSPLIT*KVL];

__device__ __forceinline__ int get_pos(const int* __restrict__ p, int b)
{
    bool is64 = (p[1] == 0) && (p[3] == 0) && (p[0] != 0);
    return is64 ? p[2*b] : p[b];
}

// ---------------- GEMV core: RW=2,U=4, smem-staged X, 8-deep LDG batch, high occupancy ----
__device__ __forceinline__ void gemv_core(const float4* __restrict__ arow0,
                                          const float4* __restrict__ arow1,
                                          const float4* __restrict__ X,
                                          float4 (*sx)[512],
                                          int K4, float acc[2][4])
{
    int tid = threadIdx.x, lane = tid & 31;
    for (int kt = 0; kt < K4; kt += 512) {
        int cur = min(512, K4 - kt);
        __syncthreads();
        for (int i = tid; i < cur; i += 256) {
            sx[0][i] = X[(size_t)0*K4 + kt + i];
            sx[1][i] = X[(size_t)1*K4 + kt + i];
            sx[2][i] = X[(size_t)2*K4 + kt + i];
            sx[3][i] = X[(size_t)3*K4 + kt + i];
        }
        __syncthreads();
        for (int ib = 0; ib < cur; ib += 128) {
            float4 av[4][2];
            #pragma unroll
            for (int u = 0; u < 4; u++) {
                av[u][0] = arow0[kt + ib + u*32 + lane];
                av[u][1] = arow1[kt + ib + u*32 + lane];
            }
            #pragma unroll
            for (int u = 0; u < 4; u++) {
                #pragma unroll
                for (int b = 0; b < 4; b++) {
                    float4 xv = sx[b][ib + u*32 + lane];
                    acc[0][b] += av[u][0].x*xv.x + av[u][0].y*xv.y
                               + av[u][0].z*xv.z + av[u][0].w*xv.w;
                    acc[1][b] += av[u][1].x*xv.x + av[u][1].y*xv.y
                               + av[u][1].z*xv.z + av[u][1].w*xv.w;
                }
            }
        }
    }
    #pragma unroll
    for (int r = 0; r < 2; r++)
        #pragma unroll
        for (int b = 0; b < 4; b++)
            #pragma unroll
            for (int off = 16; off; off >>= 1)
                acc[r][b] += __shfl_xor_sync(0xffffffffu, acc[r][b], off);
}

__global__ __launch_bounds__(256, 4)
void gemv3_kernel(const float4* __restrict__ A, const float4* __restrict__ X,
                  float* __restrict__ out, int K4, int outStride)
{
    __shared__ float4 sx[4][512];
    int tid = threadIdx.x, w = tid >> 5, lane = tid & 31;
    int row0 = (blockIdx.x * 8 + w) * 2;
    float acc[2][4] = {{0,0,0,0},{0,0,0,0}};
    gemv_core(A + (size_t)row0*K4, A + (size_t)(row0+1)*K4, X, sx, K4, acc);
    if (lane == 0) {
        #pragma unroll
        for (int r = 0; r < 2; r++)
            #pragma unroll
            for (int b = 0; b < 4; b++)
                out[(size_t)b*outStride + row0 + r] = acc[r][b];
    }
}

// dual: rows [0,QL) -> A1/out1, rows [QL,QL+QFD) -> A2/out2 (same X, same K4)
__global__ __launch_bounds__(256, 4)
void gemv3_dual_kernel(const float4* __restrict__ A1, const float4* __restrict__ A2,
                       const float4* __restrict__ X,
                       float* __restrict__ out1, float* __restrict__ out2, int K4)
{
    __shared__ float4 sx[4][512];
    int tid = threadIdx.x, w = tid >> 5, lane = tid & 31;
    int row0 = (blockIdx.x * 8 + w) * 2;
    const float4* A;
    float* out;
    int outStride, rbase;
    if (row0 < QL) { A = A1; out = out1; outStride = QL; rbase = row0; }
    else           { A = A2; out = out2; outStride = QFD; rbase = row0 - QL; }
    float acc[2][4] = {{0,0,0,0},{0,0,0,0}};
    gemv_core(A + (size_t)rbase*K4, A + (size_t)(rbase+1)*K4, X, sx, K4, acc);
    if (lane == 0) {
        #pragma unroll
        for (int r = 0; r < 2; r++)
            #pragma unroll
            for (int b = 0; b < 4; b++)
                out[(size_t)b*outStride + rbase + r] = acc[r][b];
    }
}

// ---------------- rmsnorm of q_a ----------------
__global__ void rmsnorm_q_kernel(const float* __restrict__ gamma)
{
    int b = blockIdx.x, tid = threadIdx.x;
    float ss = 0.f;
    for (int i = tid; i < QL; i += 256) { float v = g_qa[b*QL+i]; ss += v*v; }
    #pragma unroll
    for (int off = 16; off; off >>= 1) ss += __shfl_xor_sync(0xffffffffu, ss, off);
    __shared__ float r[8];
    __shared__ float s_rs;
    if ((tid & 31) == 0) r[tid >> 5] = ss;
    __syncthreads();
    if (tid == 0) {
        float t = 0.f;
        #pragma unroll
        for (int i = 0; i < 8; i++) t += r[i];
        s_rs = rsqrtf(t / (float)QL + 1e-6f);
    }
    __syncthreads();
    for (int i = tid; i < QL; i += 256) g_qan[b*QL+i] = g_qa[b*QL+i] * s_rs * gamma[i];
}

// ---------------- fused prep: transpose(past) | copy(past->out_cache) | ckv_post ----------------
#define PREP_TRANS 2304
#define PREP_COPY  2304
__global__ void prep_kernel(const float* __restrict__ past,
                            float* __restrict__ out_cache,
                            const float* __restrict__ gkv, const float* __restrict__ cosT,
                            const float* __restrict__ sinT, const int* __restrict__ posw)
{
    __shared__ float tile[32][33];
    __shared__ float red[8];
    __shared__ float s_rs;
    int blk = blockIdx.x, tid = threadIdx.x;

    if (blk < PREP_TRANS) {
        int b = blk / 576, rem = blk % 576;
        int kb = (rem / 32) * 32, tb = (rem % 32) * 32;
        int tx = tid & 31, ty = tid >> 5;
        #pragma unroll
        for (int i = ty; i < 32; i += 8)
            tile[i][tx] = past[((size_t)b*(TT-1) + tb + i)*QFD + kb + tx];
        __syncthreads();
        #pragma unroll
        for (int i = ty; i < 32; i += 8)
            g_ct[((size_t)b*QFD + kb + i)*TT + tb + tx] = tile[tx][i];
        return;
    }
    if (blk < PREP_TRANS + PREP_COPY) {
        size_t g = (size_t)(blk - PREP_TRANS) * 256 + tid;
        int b = (int)(g / 147456);
        size_t rr = g % 147456;
        int t = (int)(rr / 144), i = (int)(rr % 144);
        ((float4*)(out_cache + ((size_t)b*TT + t)*QFD))[i] =
            ((const float4*)(past + ((size_t)b*(TT-1) + t)*QFD))[i];
        return;
    }
    {
        int b = blk - (PREP_TRANS + PREP_COPY);
        const float* cv = g_ckv + b*QFD;
        float ss = 0.f;
        for (int i = tid; i < KVL; i += 256) { float v = cv[i]; ss += v*v; }
        #pragma unroll
        for (int off = 16; off; off >>= 1) ss += __shfl_xor_sync(0xffffffffu, ss, off);
        if ((tid & 31) == 0) red[tid >> 5] = ss;
        __syncthreads();
        if (tid == 0) {
            float t = 0.f;
            #pragma unroll
            for (int i = 0; i < 8; i++) t += red[i];
            s_rs = rsqrtf(t / (float)KVL + 1e-6f);
        }
        __syncthreads();
        float* dst = out_cache + ((size_t)b*TT + (TT-1)) * QFD;
        float* ctb = g_ct + (size_t)b*QFD*TT + (TT-1);
        for (int i = tid; i < KVL; i += 256) {
            float v = cv[i] * s_rs * gkv[i];
            dst[i] = v;
            ctb[(size_t)i*TT] = v;
        }
        if (tid < DR) {
            int d = tid;
            int p = get_pos(posw, b);
            float v  = cv[KVL + d];
            float pr = (d < 32) ? -cv[KVL + d + 32] : cv[KVL + d - 32];
            float res = v * cosT[(size_t)p*DR + d] + pr * sinT[(size_t)p*DR + d];
            dst[KVL + d] = res;
            ctb[(size_t)(KVL + d)*TT] = res;
        }
    }
}

// ---------------- absorption + fused q_pe RoPE -> g_qfull (pre-scaled) ----------------
__global__ void absorb_rope_kernel(const float* __restrict__ w_kvb,
                                   const float* __restrict__ cosT, const float* __restrict__ sinT,
                                   const int* __restrict__ posw)
{
    int h = blockIdx.x, c = threadIdx.x;   // 512 threads
    __shared__ float qs[4][DN];
    int b0 = c >> 7, d0 = c & 127;
    qs[b0][d0] = g_q[(size_t)b0*QROWS + h*DQK + d0];
    __syncthreads();
    float acc[4] = {0.f, 0.f, 0.f, 0.f};
    const float* wk = w_kvb + (size_t)h*256*KVL + c;
    #pragma unroll 4
    for (int d = 0; d < DN; d++) {
        float wv = wk[(size_t)d*KVL];
        acc[0] += qs[0][d]*wv; acc[1] += qs[1][d]*wv;
        acc[2] += qs[2][d]*wv; acc[3] += qs[3][d]*wv;
    }
    #pragma unroll
    for (int b = 0; b < 4; b++)
        g_qfull[((size_t)(b*HH + h))*QFD + c] = acc[b] * SCALE_QK;
    if (c < 256) {
        int b = c >> 6, d = c & 63;
        int p = get_pos(posw, b);
        const float* qp = g_q + (size_t)b*QROWS + h*DQK + DN;
        float v  = qp[d];
        float pr = (d < 32) ? -qp[d+32] : qp[d-32];
        g_qfull[((size_t)(b*HH + h))*QFD + KVL + d] =
            (v * cosT[(size_t)p*DR + d] + pr * sinT[(size_t)p*DR + d]) * SCALE_QK;
    }
}

// ---------------- attention split, 512 threads ----------------
// phase1: thread-halves split 8 heads (4 each), t = tid&255
// phase3: thread owns latent column c = tid (0..511)
__global__ __launch_bounds__(512)
void attn_split_kernel(const float* __restrict__ past,
                       const float* __restrict__ out_cache,
                       const float* __restrict__ mask)
{
    __shared__ __align__(16) float qsm[8*QFD];
    __shared__ __align__(16) float sc[8*SCP2];
    int b = blockIdx.z, split = blockIdx.y, h0 = blockIdx.x * 8, tid = threadIdx.x;
    int T0 = split * 256;
    int TE = (split == NSPLIT-1) ? TT : T0 + 256;
    int cnt = TE - T0;

    for (int i = tid; i < 8*QFD; i += 512) {
        int h = i / QFD, k = i % QFD;
        qsm[i] = g_qfull[((size_t)(b*HH + h0 + h))*QFD + k];
    }
    __syncthreads();

    // ---- phase 1: scores; half-block does 4 heads each for t = T0 + (tid&255) ----
    {
        int tq = tid & 255;
        int hb = (tid >> 8) * 4;
        float acc[4] = {0.f, 0.f, 0.f, 0.f};
        const float* ctb = g_ct + (size_t)b*QFD*TT + T0 + tq;
        for (int k = 0; k < QFD; k += 8) {
            float c[8];
            #pragma unroll
            for (int j = 0; j < 8; j++) c[j] = ctb[(size_t)(k+j)*TT];
            #pragma unroll
            for (int hh = 0; hh < 4; hh++) {
                const float4* qv = reinterpret_cast<const float4*>(&qsm[(hb+hh)*QFD + k]);
                float4 q0 = qv[0], q1 = qv[1];
                acc[hh] += q0.x*c[0] + q0.y*c[1] + q0.z*c[2] + q0.w*c[3]
                         + q1.x*c[4] + q1.y*c[5] + q1.z*c[6] + q1.w*c[7];
            }
        }
        float mk = mask[(size_t)b*TT + T0 + tq];
        #pragma unroll
        for (int hh = 0; hh < 4; hh++) sc[(hb+hh)*SCP2 + tq] = acc[hh] + mk;

        if (split == NSPLIT-1 && tid < 32) {   // t = 1024 by warp 0
            const float* crow = out_cache + ((size_t)b*TT + (TT-1))*QFD;
            float mk2 = mask[(size_t)b*TT + (TT-1)];
            for (int h = 0; h < 8; h++) {
                float p = 0.f;
                for (int i = tid; i < QFD; i += 32) p += qsm[h*QFD + i]*crow[i];
                #pragma unroll
                for (int off = 16; off; off >>= 1) p += __shfl_xor_sync(0xffffffffu, p, off);
                if (tid == 0) sc[h*SCP2 + 256] = p + mk2;
            }
        }
    }
    __syncthreads();

    // ---- phase 2: local softmax, warps 0-7 (one per head) ----
    if (tid < 256) {
        int w = tid >> 5, lane = tid & 31, h = w;
        float m = -1e30f;
        for (int t = lane; t < cnt; t += 32) m = fmaxf(m, sc[h*SCP2 + t]);
        #pragma unroll
        for (int off = 16; off; off >>= 1) m = fmaxf(m, __shfl_xor_sync(0xffffffffu, m, off));
        float s = 0.f;
        for (int t = lane; t < cnt; t += 32) {
            float e = __expf(sc[h*SCP2 + t] - m);
            sc[h*SCP2 + t] = e;
            s += e;
        }
        #pragma unroll
        for (int off = 16; off; off >>= 1) s += __shfl_xor_sync(0xffffffffu, s, off);
        if (lane == 0) {
            int idx = (b*HH + h0 + h)*NSPLIT + split;
            g_pm[idx] = m;
            g_ps[idx] = s;
        }
    }
    __syncthreads();

    // ---- phase 3: partial ctx; each thread owns latent column c = tid ----
    {
        float acc[8];
        #pragma unroll
        for (int h = 0; h < 8; h++) acc[h] = 0.f;
        const float* pb = past + (size_t)b*(TT-1)*QFD;
        int c = tid;
        for (int t0 = T0; t0 < T0 + 256; t0 += 4) {
            float v[4];
            #pragma unroll
            for (int j = 0; j < 4; j++) v[j] = pb[(size_t)(t0+j)*QFD + c];
            int tl = t0 - T0;
            #pragma unroll
            for (int h = 0; h < 8; h++) {
                float4 a4 = *reinterpret_cast<const float4*>(&sc[h*SCP2 + tl]);
                acc[h] += a4.x*v[0] + a4.y*v[1] + a4.z*v[2] + a4.w*v[3];
            }
        }
        if (TE == TT) {
            float v = out_cache[((size_t)b*TT + (TT-1))*QFD + c];
            #pragma unroll
            for (int h = 0; h < 8; h++) acc[h] += sc[h*SCP2 + 256] * v;
        }
        #pragma unroll
        for (int h = 0; h < 8; h++)
            g_pctx[((size_t)(b*HH + h0 + h)*NSPLIT + split)*KVL + c] = acc[h];
    }
}

// ---------------- fused combine + V projection; grid (HH, 2) ----------------
__global__ void vproj_combine_kernel(const float* __restrict__ w_kvb)
{
    __shared__ float cl[4][KVL];
    int h = blockIdx.x, half = blockIdx.y, tid = threadIdx.x;
    {
        int bq = tid >> 6, lq = tid & 63;
        int idx = bq*HH + h;
        float m = -1e30f;
        #pragma unroll
        for (int s = 0; s < NSPLIT; s++) m = fmaxf(m, g_pm[idx*NSPLIT + s]);
        float e[NSPLIT]; float ssum = 0.f;
        #pragma unroll
        for (int s = 0; s < NSPLIT; s++) {
            e[s] = __expf(g_pm[idx*NSPLIT + s] - m);
            ssum += g_ps[idx*NSPLIT + s] * e[s];
        }
        float inv = 1.0f / ssum;
        for (int c = lq; c < KVL; c += 64) {
            float acc = 0.f;
            #pragma unroll
            for (int s = 0; s < NSPLIT; s++)
                acc += g_pctx[((size_t)idx*NSPLIT + s)*KVL + c] * e[s];
            cl[bq][c] = acc * inv;
        }
    }
    __syncthreads();
    int w = tid >> 5, lane = tid & 31;
    int dv = half*64 + w*8;
    for (int d = dv; d < dv + 8; d++) {
        const float* wr = w_kvb + ((size_t)(h*256 + DN + d))*KVL;
        float p0 = 0.f, p1 = 0.f, p2 = 0.f, p3 = 0.f;
        #pragma unroll 4
        for (int i = lane; i < KVL; i += 32) {
            float wv = wr[i];
            p0 += wv * cl[0][i];
            p1 += wv * cl[1][i];
            p2 += wv * cl[2][i];
            p3 += wv * cl[3][i];
        }
        #pragma unroll
        for (int off = 16; off; off >>= 1) {
            p0 += __shfl_xor_sync(0xffffffffu, p0, off);
            p1 += __shfl_xor_sync(0xffffffffu, p1, off);
            p2 += __shfl_xor_sync(0xffffffffu, p2, off);
            p3 += __shfl_xor_sync(0xffffffffu, p3, off);
        }
        if (lane == 0) {
            g_ctx[(size_t)0*CTXD + h*DV + d] = p0;
            g_ctx[(size_t)1*CTXD + h*DV + d] = p1;
            g_ctx[(size_t)2*CTXD + h*DV + d] = p2;
            g_ctx[(size_t)3*CTXD + h*DV + d] = p3;
        }
    }
}

// ---------------- host launch (single stream, zero allocations) ----------------
extern "C" void kernel_launch(void* const* d_in, const int* in_sizes, int n_in,
                              void* d_out, int out_size)
{
    const float* x      = (const float*)d_in[0];
    const float* mask   = (const float*)d_in[1];
    const int*   posw   = (const int*)  d_in[2];
    const float* past   = (const float*)d_in[3];
    const float* cosT   = (const float*)d_in[4];
    const float* sinT   = (const float*)d_in[5];
    const float* w_qa   = (const float*)d_in[6];
    const float* gq     = (const float*)d_in[7];
    const float* w_qb   = (const float*)d_in[8];
    const float* w_kva  = (const float*)d_in[9];
    const float* gkv    = (const float*)d_in[10];
    const float* w_kvb  = (const float*)d_in[11];
    const float* w_o    = (const float*)d_in[12];

    float* out_attn  = (float*)d_out;                  // [4,1,7168]
    float* out_cache = out_attn + (size_t)BB*HID;      // [4,1025,576]

    float *p_qa, *p_qan, *p_q, *p_ckv, *p_ctx;
    cudaGetSymbolAddress((void**)&p_qa,  g_qa);
    cudaGetSymbolAddress((void**)&p_qan, g_qan);
    cudaGetSymbolAddress((void**)&p_q,   g_q);
    cudaGetSymbolAddress((void**)&p_ckv, g_ckv);
    cudaGetSymbolAddress((void**)&p_ctx, g_ctx);

    // q_a = x @ w_qa.T  AND  ckv = x @ w_kva.T  (one launch, 132 blocks)
    gemv3_dual_kernel<<<(QL+QFD)/16, 256>>>((const float4*)w_qa, (const float4*)w_kva,
                                            (const float4*)x, p_qa, p_ckv, HID/4);
    // rmsnorm(q_a)
    rmsnorm_q_kernel<<<BB, 256>>>(gq);
    // q = q_an @ w_qb.T        (151 MB, 1536 blocks)
    gemv3_kernel<<<QROWS/16, 256>>>((const float4*)w_qb, (const float4*)p_qan, p_q, QL/4, QROWS);
    // fused: transpose past -> g_ct | copy past -> out_cache | ckv_post
    prep_kernel<<<PREP_TRANS + PREP_COPY + BB, 256>>>(past, out_cache, gkv, cosT, sinT, posw);
    // absorption + fused q_pe RoPE
    absorb_rope_kernel<<<HH, 512>>>(w_kvb, cosT, sinT, posw);
    // attention: split-KV, 512 threads
    attn_split_kernel<<<dim3(HH/8, NSPLIT, BB), 512>>>(past, out_cache, mask);
    // combine + V projection
    vproj_combine_kernel<<<dim3(HH, 2), 256>>>(w_kvb);
    // attn_out = ctx @ w_o.T   (470 MB, 448 blocks)
    gemv3_kernel<<<HID/16, 256>>>((const float4*)w_o, (const float4*)p_ctx, out_attn, CTXD/4, HID);
}